// round 13
// baseline (speedup 1.0000x reference)
#include <cuda_runtime.h>
#include <cuda_fp16.h>
#include <cstdint>

#define DEVINL __device__ __forceinline__

// ----------------------------------------------------------------------------
// w_bin pre-packed as mma.sync m16n8k16 B-fragments (fp16, "col" operand),
// two nb per uint4 for LDS.128:
//   word idx = ((kc*8 + nb/2)*32 + lane)*4 + (nb&1)*2 + j
//   (lane = (f&7)*4 + (kk>>1), j = k-half, half = kk&1 — layout proven in R9)
// 32 KB total.
// ----------------------------------------------------------------------------
__device__ __align__(16) unsigned char g_bfrag[32768];

// ----------------------------------------------------------------------------
// Threefry2x32-20 (JAX permutation) — PARTITIONABLE output scheme (proven R8)
// ----------------------------------------------------------------------------
DEVINL uint32_t rotl32(uint32_t x, int r) { return (x << r) | (x >> (32 - r)); }

DEVINL void threefry2x32(uint32_t k0, uint32_t k1, uint32_t& x0, uint32_t& x1) {
    uint32_t ks0 = k0, ks1 = k1, ks2 = k0 ^ k1 ^ 0x1BD11BDAu;
    x0 += ks0; x1 += ks1;
#define TF_ROUND(r) { x0 += x1; x1 = rotl32(x1, r) ^ x0; }
    TF_ROUND(13) TF_ROUND(15) TF_ROUND(26) TF_ROUND(6)
    x0 += ks1; x1 += ks2 + 1u;
    TF_ROUND(17) TF_ROUND(29) TF_ROUND(16) TF_ROUND(24)
    x0 += ks2; x1 += ks0 + 2u;
    TF_ROUND(13) TF_ROUND(15) TF_ROUND(26) TF_ROUND(6)
    x0 += ks0; x1 += ks1 + 3u;
    TF_ROUND(17) TF_ROUND(29) TF_ROUND(16) TF_ROUND(24)
    x0 += ks1; x1 += ks2 + 4u;
    TF_ROUND(13) TF_ROUND(15) TF_ROUND(26) TF_ROUND(6)
    x0 += ks2; x1 += ks0 + 5u;
#undef TF_ROUND
}

// Store w_bin[d][f] (d = K index, f = N index) into B-fragment layout (fp16).
DEVINL void wbin_store(int lin_idx, float s) {
    int d = lin_idx >> 7;      // weight row  -> k
    int f = lin_idx & 127;     // weight col  -> n
    int kc = d >> 4, dk = d & 15;
    int nb = f >> 3;
    int j    = dk >> 3;
    int kk   = dk & 7;
    int lane = (f & 7) * 4 + (kk >> 1);
    int half = kk & 1;
    uint32_t widx = (uint32_t)((((kc * 8 + (nb >> 1)) * 32 + lane) * 4) +
                               ((nb & 1) * 2 + j));
    *(__half*)(g_bfrag + widx * 4 + half * 2) = __float2half_rn(s);
}

// Partitionable threefry: element i -> counter (0, i), bits = out0 ^ out1.
__global__ void wbin_kernel(const float* __restrict__ weight,
                            const int* __restrict__ seed_p,
                            const int* __restrict__ train_p) {
    int i = blockIdx.x * blockDim.x + threadIdx.x;
    if (i >= 16384) return;
    float s;
    if (*train_p) {
        uint32_t x0 = 0u, x1 = (uint32_t)i;
        threefry2x32(0u, (uint32_t)(*seed_p), x0, x1);
        uint32_t bits = x0 ^ x1;
        float u = __uint_as_float(0x3f800000u | (bits >> 9)) - 1.0f;
        float w = weight[i];
        float p = fminf(fmaxf(__fmul_rn(__fadd_rn(w, 1.0f), 0.5f), 0.0f), 1.0f);
        s = (u < p) ? 1.0f : -1.0f;
    } else {
        s = (weight[i] > 0.0f) ? 1.0f : -1.0f;
    }
    wbin_store(i, s);
}

// ----------------------------------------------------------------------------
// mma / ldmatrix helpers (fp16 single-precision-split-free path)
// ----------------------------------------------------------------------------
DEVINL uint32_t smem_u32(const void* p) {
    uint32_t a;
    asm("{ .reg .u64 t; cvta.to.shared.u64 t, %1; cvt.u32.u64 %0, t; }"
        : "=r"(a) : "l"(p));
    return a;
}

DEVINL void ldmatrix_x4(uint32_t& r0, uint32_t& r1, uint32_t& r2, uint32_t& r3,
                        uint32_t addr) {
    asm volatile("ldmatrix.sync.aligned.m8n8.x4.shared.b16 {%0,%1,%2,%3}, [%4];"
                 : "=r"(r0), "=r"(r1), "=r"(r2), "=r"(r3) : "r"(addr));
}

DEVINL void mma_f16(float& c0, float& c1, float& c2, float& c3,
                    uint32_t a0, uint32_t a1, uint32_t a2, uint32_t a3,
                    uint32_t b0, uint32_t b1) {
    asm volatile(
        "mma.sync.aligned.m16n8k16.row.col.f32.f16.f16.f32 "
        "{%0,%1,%2,%3}, {%4,%5,%6,%7}, {%8,%9}, {%0,%1,%2,%3};"
        : "+f"(c0), "+f"(c1), "+f"(c2), "+f"(c3)
        : "r"(a0), "r"(a1), "r"(a2), "r"(a3), "r"(b0), "r"(b1));
}

// ----------------------------------------------------------------------------
// GEMM kernel: one 128x128 output tile per CTA, 256 threads (8 warps).
// Warp w computes rows [16w, 16w+16) x all 128 cols.
// A: coalesced LDG.128 -> fp16 cvt -> 32B-granule XOR-swizzled SMEM
//    (layout identical to R9's proven path; bf16->fp16 is size-neutral),
//    then ONE ldmatrix.x4 per kc.
// B: 32 KB fragment copy; two nb per LDS.128.
// ----------------------------------------------------------------------------
__global__ void __launch_bounds__(256, 2)
gemm_kernel(const float* __restrict__ inp, float* __restrict__ out) {
    __shared__ __align__(16) unsigned char smemA[32768];
    __shared__ __align__(16) unsigned char smemB[32768];
    const int tid  = threadIdx.x;
    const int w    = tid >> 5;
    const int lane = tid & 31;

    // --- B fragments: straight 32 KB copy (L2-resident, shared by all CTAs) ---
    {
        const uint4* src = (const uint4*)g_bfrag;
        uint4* dst = (uint4*)smemB;
#pragma unroll
        for (int i = 0; i < 8; i++) dst[tid + i * 256] = src[tid + i * 256];
    }

    // --- A tile: coalesced float4 loads -> fp16x4 -> swizzled SMEM (8B STS) ---
    {
        const float4* a4 = (const float4*)(inp + (size_t)blockIdx.x * 16384);
#pragma unroll
        for (int i = 0; i < 16; i++) {
            int idx = tid + i * 256;
            int row = idx >> 5;
            int c4  = idx & 31;       // float4 index within row
            float4 v = __ldcs(a4 + idx);
            uint32_t h01, h23;
            asm("cvt.rn.f16x2.f32 %0, %1, %2;" : "=r"(h01) : "f"(v.y), "f"(v.x));
            asm("cvt.rn.f16x2.f32 %0, %1, %2;" : "=r"(h23) : "f"(v.w), "f"(v.z));
            uint32_t off = (uint32_t)(row * 256 + ((((c4 >> 2) ^ (row & 7))) << 5) +
                                      ((c4 & 3) << 3));
            *(uint2*)(smemA + off) = make_uint2(h01, h23);
        }
    }
    __syncthreads();

    // --- ldmatrix per-lane base address for this warp's 16-row slice ---
    const int arow = 16 * w + (lane & 15);
    const uint32_t a_base = smem_u32(smemA) +
                            (uint32_t)(arow * 256 + ((lane >> 4) << 4));
    const uint32_t a_sw = (uint32_t)(arow & 7);

    const uint4* bfr = (const uint4*)smemB;

    float c[16][4];
#pragma unroll
    for (int nb = 0; nb < 16; nb++)
#pragma unroll
        for (int q = 0; q < 4; q++) c[nb][q] = 0.0f;

    // --- Main loop over K chunks: 1 ldmatrix + 8 LDS.128 + 16 MMA ---
#pragma unroll
    for (int kc = 0; kc < 8; kc++) {
        uint32_t koff = (uint32_t)(((uint32_t)kc ^ a_sw) << 5);
        uint32_t a0, a1, a2, a3;
        ldmatrix_x4(a0, a1, a2, a3, a_base + koff);

        const uint4* bk = bfr + kc * 8 * 32 + lane;
#pragma unroll
        for (int nbp = 0; nbp < 8; nbp++) {
            uint4 b = bk[nbp * 32];
            mma_f16(c[2 * nbp][0], c[2 * nbp][1], c[2 * nbp][2], c[2 * nbp][3],
                    a0, a1, a2, a3, b.x, b.y);
            mma_f16(c[2 * nbp + 1][0], c[2 * nbp + 1][1],
                    c[2 * nbp + 1][2], c[2 * nbp + 1][3],
                    a0, a1, a2, a3, b.z, b.w);
        }
    }

    // --- Epilogue: direct streaming STG.64 (full 32B sectors per 4 lanes) ---
    {
        const int orow = (int)(blockIdx.x * 128) + 16 * w + (lane >> 2);
        const int cb = 2 * (lane & 3);
        float* o0 = out + (size_t)orow * 128 + cb;
        float* o1 = o0 + (size_t)8 * 128;
#pragma unroll
        for (int nb = 0; nb < 16; nb++) {
            __stcs((float2*)(o0 + nb * 8), make_float2(c[nb][0], c[nb][1]));
            __stcs((float2*)(o1 + nb * 8), make_float2(c[nb][2], c[nb][3]));
        }
    }
}

// ----------------------------------------------------------------------------
extern "C" void kernel_launch(void* const* d_in, const int* in_sizes, int n_in,
                              void* d_out, int out_size) {
    // Resolve pointers by size (robust to metadata ordering).
    int ii = 0, wi = 1, si = 2, ti = 3;
    {
        int small[4]; int ns = 0;
        for (int i = 0; i < n_in; i++) {
            if (in_sizes[i] == 16384) wi = i;
            else if (in_sizes[i] > 100000) ii = i;
            else if (ns < 4) small[ns++] = i;
        }
        if (ns >= 2) { si = small[0]; ti = small[1]; }
        else if (ns == 1) { si = small[0]; ti = small[0]; }
    }
    const float* inputs = (const float*)d_in[ii];
    const float* weight = (const float*)d_in[wi];
    const int*   seed   = (const int*)d_in[si];
    const int*   train  = (const int*)d_in[ti];
    float* out = (float*)d_out;

    int n_rows  = in_sizes[ii] / 128;   // 1048576
    int n_tiles = n_rows / 128;         // 8192

    wbin_kernel<<<64, 256>>>(weight, seed, train);
    gemm_kernel<<<n_tiles, 256>>>(inputs, out);
}

// round 15
// speedup vs baseline: 1.3296x; 1.3296x over previous
#include <cuda_runtime.h>
#include <cuda_fp16.h>
#include <cstdint>

#define DEVINL __device__ __forceinline__

// ----------------------------------------------------------------------------
// w_bin pre-packed as mma.sync m16n8k16 B-fragments (fp16, "col" operand),
// two nb per uint4 for LDS.128:
//   word idx = ((kc*8 + nb/2)*32 + lane)*4 + (nb&1)*2 + j
//   (lane = (f&7)*4 + (kk>>1), j = k-half, half = kk&1 — proven R9/R13)
// 32 KB total.
// ----------------------------------------------------------------------------
__device__ __align__(16) unsigned char g_bfrag[32768];

// ----------------------------------------------------------------------------
// Threefry2x32-20 (JAX permutation) — PARTITIONABLE output scheme (proven R8)
// ----------------------------------------------------------------------------
DEVINL uint32_t rotl32(uint32_t x, int r) { return (x << r) | (x >> (32 - r)); }

DEVINL void threefry2x32(uint32_t k0, uint32_t k1, uint32_t& x0, uint32_t& x1) {
    uint32_t ks0 = k0, ks1 = k1, ks2 = k0 ^ k1 ^ 0x1BD11BDAu;
    x0 += ks0; x1 += ks1;
#define TF_ROUND(r) { x0 += x1; x1 = rotl32(x1, r) ^ x0; }
    TF_ROUND(13) TF_ROUND(15) TF_ROUND(26) TF_ROUND(6)
    x0 += ks1; x1 += ks2 + 1u;
    TF_ROUND(17) TF_ROUND(29) TF_ROUND(16) TF_ROUND(24)
    x0 += ks2; x1 += ks0 + 2u;
    TF_ROUND(13) TF_ROUND(15) TF_ROUND(26) TF_ROUND(6)
    x0 += ks0; x1 += ks1 + 3u;
    TF_ROUND(17) TF_ROUND(29) TF_ROUND(16) TF_ROUND(24)
    x0 += ks1; x1 += ks2 + 4u;
    TF_ROUND(13) TF_ROUND(15) TF_ROUND(26) TF_ROUND(6)
    x0 += ks2; x1 += ks0 + 5u;
#undef TF_ROUND
}

// Store w_bin[d][f] (d = K index, f = N index) into B-fragment layout (fp16).
DEVINL void wbin_store(int lin_idx, float s) {
    int d = lin_idx >> 7;      // weight row  -> k
    int f = lin_idx & 127;     // weight col  -> n
    int kc = d >> 4, dk = d & 15;
    int nb = f >> 3;
    int j    = dk >> 3;
    int kk   = dk & 7;
    int lane = (f & 7) * 4 + (kk >> 1);
    int half = kk & 1;
    uint32_t widx = (uint32_t)((((kc * 8 + (nb >> 1)) * 32 + lane) * 4) +
                               ((nb & 1) * 2 + j));
    *(__half*)(g_bfrag + widx * 4 + half * 2) = __float2half_rn(s);
}

// Partitionable threefry: element i -> counter (0, i), bits = out0 ^ out1.
__global__ void wbin_kernel(const float* __restrict__ weight,
                            const int* __restrict__ seed_p,
                            const int* __restrict__ train_p) {
    int i = blockIdx.x * blockDim.x + threadIdx.x;
    if (i >= 16384) return;
    float s;
    if (*train_p) {
        uint32_t x0 = 0u, x1 = (uint32_t)i;
        threefry2x32(0u, (uint32_t)(*seed_p), x0, x1);
        uint32_t bits = x0 ^ x1;
        float u = __uint_as_float(0x3f800000u | (bits >> 9)) - 1.0f;
        float w = weight[i];
        float p = fminf(fmaxf(__fmul_rn(__fadd_rn(w, 1.0f), 0.5f), 0.0f), 1.0f);
        s = (u < p) ? 1.0f : -1.0f;
    } else {
        s = (weight[i] > 0.0f) ? 1.0f : -1.0f;
    }
    wbin_store(i, s);
}

// ----------------------------------------------------------------------------
// mma helper (fp16, fp32 accumulate)
// ----------------------------------------------------------------------------
DEVINL void mma_f16(float& c0, float& c1, float& c2, float& c3,
                    uint32_t a0, uint32_t a1, uint32_t a2, uint32_t a3,
                    uint32_t b0, uint32_t b1) {
    asm volatile(
        "mma.sync.aligned.m16n8k16.row.col.f32.f16.f16.f32 "
        "{%0,%1,%2,%3}, {%4,%5,%6,%7}, {%8,%9}, {%0,%1,%2,%3};"
        : "+f"(c0), "+f"(c1), "+f"(c2), "+f"(c3)
        : "r"(a0), "r"(a1), "r"(a2), "r"(a3), "r"(b0), "r"(b1));
}

DEVINL uint32_t f16x2(float x, float y) {
    uint32_t h;
    asm("cvt.rn.f16x2.f32 %0, %1, %2;" : "=r"(h) : "f"(y), "f"(x));
    return h;
}

// ----------------------------------------------------------------------------
// GEMM kernel: one 128x128 output tile per CTA, 256 threads (8 warps).
// Warp w computes rows [16w, 16w+16) x all 128 cols.
// A loaded DIRECTLY from GMEM in fragment layout (R11's proven-cheapest path):
//   lane l, chunk kc: rows 16w + l/4 and +8, cols kc*16 + 2(l&3) (+1) and +8.
//   Lanes 0-3 cover one full 32B sector of a row; across kc the full row is
//   consumed exactly once -> 100% sector efficiency.
// fp16 single MMA (rel_err 2.1e-4, proven R13). B: 32 KB SMEM, LDS.128.
// ----------------------------------------------------------------------------
__global__ void __launch_bounds__(256, 2)
gemm_kernel(const float* __restrict__ inp, float* __restrict__ out) {
    __shared__ __align__(16) unsigned char smemB[32768];
    const int tid  = threadIdx.x;
    const int w    = tid >> 5;
    const int lane = tid & 31;

    // --- B fragments: straight 32 KB copy (L2-resident, shared by all CTAs) ---
    {
        const uint4* src = (const uint4*)g_bfrag;
        uint4* dst = (uint4*)smemB;
#pragma unroll
        for (int i = 0; i < 8; i++) dst[tid + i * 256] = src[tid + i * 256];
    }
    __syncthreads();

    const int r0 = 16 * w + (lane >> 2);
    const float* a0p = inp + (size_t)blockIdx.x * 16384 + (size_t)r0 * 128 + (lane & 3) * 2;
    const float* a8p = a0p + 8 * 128;
    const uint4* bfr = (const uint4*)smemB;

    float c[16][4];
#pragma unroll
    for (int nb = 0; nb < 16; nb++)
#pragma unroll
        for (int q = 0; q < 4; q++) c[nb][q] = 0.0f;

    // Prefetched A pairs: x00 = (r0, k+0..1), x01 = (r0, k+8..9),
    //                     x10 = (r0+8, k+0..1), x11 = (r0+8, k+8..9)
    float2 x00 = __ldcs((const float2*)(a0p));
    float2 x01 = __ldcs((const float2*)(a0p + 8));
    float2 x10 = __ldcs((const float2*)(a8p));
    float2 x11 = __ldcs((const float2*)(a8p + 8));

#pragma unroll
    for (int kc = 0; kc < 8; kc++) {
        float2 n00, n01, n10, n11;
        if (kc < 7) {
            const float* p0 = a0p + (kc + 1) * 16;
            const float* p8 = a8p + (kc + 1) * 16;
            n00 = __ldcs((const float2*)(p0));
            n01 = __ldcs((const float2*)(p0 + 8));
            n10 = __ldcs((const float2*)(p8));
            n11 = __ldcs((const float2*)(p8 + 8));
        }

        // Fragment order: a0=(r0,k0) a1=(r0+8,k0) a2=(r0,k8) a3=(r0+8,k8)
        uint32_t a0 = f16x2(x00.x, x00.y);
        uint32_t a1 = f16x2(x10.x, x10.y);
        uint32_t a2 = f16x2(x01.x, x01.y);
        uint32_t a3 = f16x2(x11.x, x11.y);

        const uint4* bk = bfr + kc * 8 * 32 + lane;
#pragma unroll
        for (int nbp = 0; nbp < 8; nbp++) {
            uint4 b = bk[nbp * 32];
            mma_f16(c[2 * nbp][0], c[2 * nbp][1], c[2 * nbp][2], c[2 * nbp][3],
                    a0, a1, a2, a3, b.x, b.y);
            mma_f16(c[2 * nbp + 1][0], c[2 * nbp + 1][1],
                    c[2 * nbp + 1][2], c[2 * nbp + 1][3],
                    a0, a1, a2, a3, b.z, b.w);
        }

        x00 = n00; x01 = n01; x10 = n10; x11 = n11;
    }

    // --- Epilogue: direct streaming STG.64 (full 32B sectors per 4 lanes) ---
    {
        const int orow = (int)(blockIdx.x * 128) + 16 * w + (lane >> 2);
        const int cb = 2 * (lane & 3);
        float* o0 = out + (size_t)orow * 128 + cb;
        float* o1 = o0 + (size_t)8 * 128;
#pragma unroll
        for (int nb = 0; nb < 16; nb++) {
            __stcs((float2*)(o0 + nb * 8), make_float2(c[nb][0], c[nb][1]));
            __stcs((float2*)(o1 + nb * 8), make_float2(c[nb][2], c[nb][3]));
        }
    }
}

// ----------------------------------------------------------------------------
extern "C" void kernel_launch(void* const* d_in, const int* in_sizes, int n_in,
                              void* d_out, int out_size) {
    // Resolve pointers by size (robust to metadata ordering).
    int ii = 0, wi = 1, si = 2, ti = 3;
    {
        int small[4]; int ns = 0;
        for (int i = 0; i < n_in; i++) {
            if (in_sizes[i] == 16384) wi = i;
            else if (in_sizes[i] > 100000) ii = i;
            else if (ns < 4) small[ns++] = i;
        }
        if (ns >= 2) { si = small[0]; ti = small[1]; }
        else if (ns == 1) { si = small[0]; ti = small[0]; }
    }
    const float* inputs = (const float*)d_in[ii];
    const float* weight = (const float*)d_in[wi];
    const int*   seed   = (const int*)d_in[si];
    const int*   train  = (const int*)d_in[ti];
    float* out = (float*)d_out;

    int n_rows  = in_sizes[ii] / 128;   // 1048576
    int n_tiles = n_rows / 128;         // 8192

    wbin_kernel<<<64, 256>>>(weight, seed, train);
    gemm_kernel<<<n_tiles, 256>>>(inputs, out);
}